// round 1
// baseline (speedup 1.0000x reference)
#include <cuda_runtime.h>
#include <math.h>

#define ETA 0.1f
#define NM 64
#define NN 4096            // 64*64
#define THREADS 256
#define THETA13 4.25f      // single-precision Pade-13 theta (Higham)

// ---------------------------------------------------------------------------
// 64x64 fp32 GEMM, C = A*B. 256 threads, each computes a 4x4 tile.
// All operands in shared memory. C must not alias A or B.
// ---------------------------------------------------------------------------
__device__ __forceinline__ void mm64(float* __restrict__ C,
                                     const float* __restrict__ A,
                                     const float* __restrict__ B) {
    const int tid = threadIdx.x;
    const int tx = tid & 15, ty = tid >> 4;
    const int r0 = ty << 2, c0 = tx << 2;
    float acc[4][4];
#pragma unroll
    for (int i = 0; i < 4; i++)
#pragma unroll
        for (int j = 0; j < 4; j++) acc[i][j] = 0.0f;

#pragma unroll 8
    for (int k = 0; k < NM; k++) {
        const float4 bv = *reinterpret_cast<const float4*>(B + (k << 6) + c0);
#pragma unroll
        for (int i = 0; i < 4; i++) {
            const float a = A[((r0 + i) << 6) + k];
            acc[i][0] = fmaf(a, bv.x, acc[i][0]);
            acc[i][1] = fmaf(a, bv.y, acc[i][1]);
            acc[i][2] = fmaf(a, bv.z, acc[i][2]);
            acc[i][3] = fmaf(a, bv.w, acc[i][3]);
        }
    }
#pragma unroll
    for (int i = 0; i < 4; i++) {
        *reinterpret_cast<float4*>(C + ((r0 + i) << 6) + c0) =
            make_float4(acc[i][0], acc[i][1], acc[i][2], acc[i][3]);
    }
}

__global__ void __launch_bounds__(THREADS, 2)
meg_update_kernel(const float* __restrict__ gR,
                  const float* __restrict__ gG,
                  float* __restrict__ gOut) {
    const int tid = threadIdx.x;
    const size_t base = (size_t)blockIdx.x * NN;
    const float* Rb = gR + base;
    const float* Gb = gG + base;
    float* Ob = gOut + base;

    extern __shared__ float sm[];
    float* bA  = sm;             // B0
    float* bA2 = sm + 1 * NN;    // B1
    float* bA4 = sm + 2 * NN;    // B2
    float* bA6 = sm + 3 * NN;    // B3
    float* bT  = sm + 4 * NN;    // B4 (scratch / U)
    float* bW  = sm + 5 * NN;    // B5 (scratch / V)

    __shared__ int s_squarings;

    // ---- Load grad into smem (for transpose access) ----
    for (int e = tid; e < NN; e += THREADS) bW[e] = Gb[e];
    __syncthreads();

    // ---- A = log(R) - ETA * (G - G^T) ----
    for (int e = tid; e < NN; e += THREADS) {
        const int i = e >> 6, j = e & 63;
        const float skew = bW[(i << 6) + j] - bW[(j << 6) + i];
        bA[e] = logf(Rb[e]) - ETA * skew;
    }
    __syncthreads();

    // ---- inf-norm (max row sum of |A|): 4 partials per row ----
    {
        float p = 0.0f;
        const int s0 = tid * 16;
#pragma unroll
        for (int q = 0; q < 16; q++) p += fabsf(bA[s0 + q]);
        bT[tid] = p;  // partial[tid]: quarter-row sums, row = tid/4
        __syncthreads();
        if (tid < 64) {
            bW[tid] = bT[4 * tid] + bT[4 * tid + 1] + bT[4 * tid + 2] + bT[4 * tid + 3];
        }
        __syncthreads();
        // max-reduce 64 row sums
        for (int off = 32; off > 0; off >>= 1) {
            if (tid < off) bW[tid] = fmaxf(bW[tid], bW[tid + off]);
            __syncthreads();
        }
        if (tid == 0) {
            const float nrm = bW[0];
            int s = 0;
            if (nrm > THETA13 && isfinite(nrm)) {
                s = (int)ceilf(log2f(nrm / THETA13));
                if (s < 0) s = 0;
                if (s > 30) s = 30;
            }
            s_squarings = s;
        }
        __syncthreads();
    }
    const int nsq = s_squarings;
    const float scale = exp2f((float)-nsq);

    // ---- scale A ----
    for (int e = tid; e < NN; e += THREADS) bA[e] *= scale;
    __syncthreads();

    // ---- powers ----
    mm64(bA2, bA, bA);   __syncthreads();
    mm64(bA4, bA2, bA2); __syncthreads();
    mm64(bA6, bA2, bA4); __syncthreads();

    // Pade-13 coefficients
    const float b0 = 64764752532480000.f, b1 = 32382376266240000.f;
    const float b2 = 7771770303897600.f,  b3 = 1187353796428800.f;
    const float b4 = 129060195264000.f,   b5 = 10559470521600.f;
    const float b6 = 670442572800.f,      b7 = 33522128640.f;
    const float b8 = 1323241920.f,        b9 = 40840800.f;
    const float b10 = 960960.f,           b11 = 16380.f;
    const float b12 = 182.f,              b13 = 1.f;

    // ---- U = A * (A6*(b13*A6 + b11*A4 + b9*A2) + b7*A6 + b5*A4 + b3*A2 + b1*I)
    for (int e = tid; e < NN; e += THREADS)
        bT[e] = b13 * bA6[e] + b11 * bA4[e] + b9 * bA2[e];
    __syncthreads();
    mm64(bW, bA6, bT);
    __syncthreads();
    for (int e = tid; e < NN; e += THREADS) {
        float v = bW[e] + b7 * bA6[e] + b5 * bA4[e] + b3 * bA2[e];
        if ((e >> 6) == (e & 63)) v += b1;
        bW[e] = v;
    }
    __syncthreads();
    mm64(bT, bA, bW);   // U -> bT
    __syncthreads();

    // ---- V = A6*(b12*A6 + b10*A4 + b8*A2) + b6*A6 + b4*A4 + b2*A2 + b0*I
    for (int e = tid; e < NN; e += THREADS)
        bA[e] = b12 * bA6[e] + b10 * bA4[e] + b8 * bA2[e];   // A dead, reuse
    __syncthreads();
    mm64(bW, bA6, bA);
    __syncthreads();
    for (int e = tid; e < NN; e += THREADS) {
        float v = bW[e] + b6 * bA6[e] + b4 * bA4[e] + b2 * bA2[e];
        if ((e >> 6) == (e & 63)) v += b0;
        bW[e] = v;       // V -> bW
    }
    __syncthreads();

    // ---- P = V - U (bA2), Q = V + U (bA4) ----
    for (int e = tid; e < NN; e += THREADS) {
        const float u = bT[e], v = bW[e];
        bA2[e] = v - u;
        bA4[e] = v + u;
    }
    __syncthreads();

    // ---- Solve P * X = Q via Gaussian elimination w/ partial pivoting ----
    {
        float* P = bA2;
        float* Q = bA4;
        float* red  = bT;                 // 64 floats
        int*   redi = (int*)(bT + 64);    // 64 ints
        float* mArr = bT + 128;           // 64 multipliers

        for (int k = 0; k < NM; k++) {
            // pivot search in column k, rows >= k
            if (tid < 64) {
                red[tid]  = (tid >= k) ? fabsf(P[(tid << 6) + k]) : -1.0f;
                redi[tid] = tid;
            }
            __syncthreads();
            for (int off = 32; off > 0; off >>= 1) {
                if (tid < off && red[tid + off] > red[tid]) {
                    red[tid]  = red[tid + off];
                    redi[tid] = redi[tid + off];
                }
                __syncthreads();
            }
            const int piv = redi[0];
            if (piv != k) {
                if (tid < 64) {
                    const float t1 = P[(k << 6) + tid];
                    P[(k << 6) + tid] = P[(piv << 6) + tid];
                    P[(piv << 6) + tid] = t1;
                } else if (tid < 128) {
                    const int j = tid - 64;
                    const float t1 = Q[(k << 6) + j];
                    Q[(k << 6) + j] = Q[(piv << 6) + j];
                    Q[(piv << 6) + j] = t1;
                }
                __syncthreads();
            }
            const float invp = 1.0f / P[(k << 6) + k];
            if (tid > k && tid < 64) mArr[tid] = P[(tid << 6) + k] * invp;
            __syncthreads();

            const int wid = tid >> 5, lane = tid & 31;
            for (int i = k + 1 + wid; i < NM; i += 8) {
                const float mi = mArr[i];
#pragma unroll
                for (int jj = 0; jj < 2; jj++) {
                    const int j = lane + (jj << 5);
                    if (j > k) P[(i << 6) + j] = fmaf(-mi, P[(k << 6) + j], P[(i << 6) + j]);
                }
#pragma unroll
                for (int jj = 0; jj < 2; jj++) {
                    const int j = lane + (jj << 5);
                    Q[(i << 6) + j] = fmaf(-mi, Q[(k << 6) + j], Q[(i << 6) + j]);
                }
            }
            __syncthreads();
        }

        // back substitution: X stored into Q in place
        float* red4 = bT;   // 256 floats scratch
        const int j = tid & 63, part = tid >> 6;
        for (int k = NM - 1; k >= 0; k--) {
            float ssum = 0.0f;
            for (int i = k + 1 + part; i < NM; i += 4)
                ssum = fmaf(P[(k << 6) + i], Q[(i << 6) + j], ssum);
            red4[(part << 6) + j] = ssum;
            __syncthreads();
            if (tid < 64) {
                const float tot = red4[tid] + red4[64 + tid] + red4[128 + tid] + red4[192 + tid];
                Q[(k << 6) + tid] = (Q[(k << 6) + tid] - tot) / P[(k << 6) + k];
            }
            __syncthreads();
        }
    }

    // ---- Squarings: X = X^(2^s). X currently in bA4. Ping-pong bA4 <-> bA6
    float* src = bA4;
    float* dst = bA6;
    for (int t = 0; t < nsq; t++) {
        mm64(dst, src, src);
        __syncthreads();
        float* tmp = src; src = dst; dst = tmp;
    }

    // ---- Write result ----
    for (int e = tid; e < NN; e += THREADS) Ob[e] = src[e];
}

extern "C" void kernel_launch(void* const* d_in, const int* in_sizes, int n_in,
                              void* d_out, int out_size) {
    const float* R = (const float*)d_in[0];
    const float* G = (const float*)d_in[1];
    float* out = (float*)d_out;

    const int batch = in_sizes[0] / NN;   // 8192
    const size_t smem = 6 * NN * sizeof(float);  // 96 KB

    static bool attr_set = false;
    if (!attr_set) {
        cudaFuncSetAttribute(meg_update_kernel,
                             cudaFuncAttributeMaxDynamicSharedMemorySize,
                             (int)smem);
        attr_set = true;
    }

    meg_update_kernel<<<batch, THREADS, smem>>>(R, G, out);
}

// round 2
// speedup vs baseline: 2.8305x; 2.8305x over previous
#include <cuda_runtime.h>
#include <math.h>

#define ETA 0.1f
#define NM 64
#define NN 4096            // 64*64
#define THREADS 256
#define THETA 2.0f         // Taylor-16 scaling threshold

typedef unsigned long long u64;

// packed fp32x2 FMA (sm_100+): d = a*b + c elementwise on 2 packed floats
__device__ __forceinline__ u64 fma2(u64 a, u64 b, u64 c) {
    u64 d;
    asm("fma.rn.f32x2 %0, %1, %2, %3;" : "=l"(d) : "l"(a), "l"(b), "l"(c));
    return d;
}
__device__ __forceinline__ u64 dup2(float a) {
    u64 d;
    asm("mov.b64 %0, {%1, %1};" : "=l"(d) : "f"(a));
    return d;
}
__device__ __forceinline__ float2 unpk(u64 v) {
    float2 r;
    asm("mov.b64 {%0, %1}, %2;" : "=f"(r.x), "=f"(r.y) : "l"(v));
    return r;
}

// ---------------------------------------------------------------------------
// 64x64 fp32 GEMM, C = A*B (+ optional epilogue d0*I + d1*E1 + d2*E2 + d3*E3).
// 256 threads, each computes a 4x4 tile. Packed f32x2 accumulation.
// All operands in shared memory. C must not alias A or B.
// ---------------------------------------------------------------------------
template<bool EPI>
__device__ __forceinline__ void mm64(float* __restrict__ C,
                                     const float* __restrict__ A,
                                     const float* __restrict__ B,
                                     const float* __restrict__ E1 = nullptr,
                                     const float* __restrict__ E2 = nullptr,
                                     const float* __restrict__ E3 = nullptr,
                                     float d0 = 0.f, float d1 = 0.f,
                                     float d2 = 0.f, float d3 = 0.f)
{
    const int tid = threadIdx.x;
    const int tx = tid & 15, ty = tid >> 4;
    const int r0 = ty << 2, c0 = tx << 2;

    u64 acc[4][2];
#pragma unroll
    for (int i = 0; i < 4; i++) { acc[i][0] = 0ull; acc[i][1] = 0ull; }

#pragma unroll 2
    for (int k0 = 0; k0 < NM; k0 += 4) {
        float4 av[4];
        ulonglong2 bv[4];
#pragma unroll
        for (int i = 0; i < 4; i++)
            av[i] = *reinterpret_cast<const float4*>(A + ((r0 + i) << 6) + k0);
#pragma unroll
        for (int kk = 0; kk < 4; kk++)
            bv[kk] = *reinterpret_cast<const ulonglong2*>(B + ((k0 + kk) << 6) + c0);
#pragma unroll
        for (int kk = 0; kk < 4; kk++) {
#pragma unroll
            for (int i = 0; i < 4; i++) {
                const float a = reinterpret_cast<const float*>(&av[i])[kk];
                const u64 aa = dup2(a);
                acc[i][0] = fma2(aa, bv[kk].x, acc[i][0]);
                acc[i][1] = fma2(aa, bv[kk].y, acc[i][1]);
            }
        }
    }

    if (!EPI) {
#pragma unroll
        for (int i = 0; i < 4; i++) {
            *reinterpret_cast<ulonglong2*>(C + ((r0 + i) << 6) + c0) =
                make_ulonglong2(acc[i][0], acc[i][1]);
        }
    } else {
#pragma unroll
        for (int i = 0; i < 4; i++) {
            const int row = r0 + i;
            const float2 p0 = unpk(acc[i][0]);
            const float2 p1 = unpk(acc[i][1]);
            const float4 e1 = *reinterpret_cast<const float4*>(E1 + (row << 6) + c0);
            const float4 e2 = *reinterpret_cast<const float4*>(E2 + (row << 6) + c0);
            const float4 e3 = *reinterpret_cast<const float4*>(E3 + (row << 6) + c0);
            float4 o;
            o.x = p0.x + fmaf(d1, e1.x, fmaf(d2, e2.x, d3 * e3.x));
            o.y = p0.y + fmaf(d1, e1.y, fmaf(d2, e2.y, d3 * e3.y));
            o.z = p1.x + fmaf(d1, e1.z, fmaf(d2, e2.z, d3 * e3.z));
            o.w = p1.y + fmaf(d1, e1.w, fmaf(d2, e2.w, d3 * e3.w));
            if (row == c0)          o.x += d0;
            else if (row == c0 + 1) o.y += d0;
            else if (row == c0 + 2) o.z += d0;
            else if (row == c0 + 3) o.w += d0;
            *reinterpret_cast<float4*>(C + (row << 6) + c0) = o;
        }
    }
}

__global__ void __launch_bounds__(THREADS, 2)
meg_update_kernel(const float* __restrict__ gR,
                  const float* __restrict__ gG,
                  float* __restrict__ gOut) {
    const int tid = threadIdx.x;
    const size_t base = (size_t)blockIdx.x * NN;
    const float* Rb = gR + base;
    const float* Gb = gG + base;
    float* Ob = gOut + base;

    extern __shared__ float sm[];
    float* bA  = sm;             // scaled A
    float* bA2 = sm + 1 * NN;
    float* bA3 = sm + 2 * NN;
    float* bA4 = sm + 3 * NN;
    float* bS  = sm + 4 * NN;    // scratch / ping
    float* bS2 = sm + 5 * NN;    // scratch / pong

    __shared__ int s_squarings;

    // ---- Load grad into smem (for transpose access) ----
    for (int e = tid; e < NN; e += THREADS) bA2[e] = Gb[e];
    __syncthreads();

    // ---- A = log(R) - ETA * (G - G^T) ----
    for (int e = tid; e < NN; e += THREADS) {
        const int i = e >> 6, j = e & 63;
        const float skew = bA2[(i << 6) + j] - bA2[(j << 6) + i];
        bA[e] = logf(Rb[e]) - ETA * skew;
    }
    __syncthreads();

    // ---- inf-norm (max row sum of |A|) -> squaring count ----
    {
        float p = 0.0f;
        const int s0 = tid * 16;
#pragma unroll
        for (int q = 0; q < 16; q++) p += fabsf(bA[s0 + q]);
        bS[tid] = p;              // quarter-row partials, row = tid/4
        __syncthreads();
        if (tid < 64)
            bS2[tid] = bS[4 * tid] + bS[4 * tid + 1] + bS[4 * tid + 2] + bS[4 * tid + 3];
        __syncthreads();
        for (int off = 32; off > 0; off >>= 1) {
            if (tid < off) bS2[tid] = fmaxf(bS2[tid], bS2[tid + off]);
            __syncthreads();
        }
        if (tid == 0) {
            const float nrm = bS2[0];
            int s = 0;
            if (nrm > THETA && isfinite(nrm)) {
                s = (int)ceilf(log2f(nrm / THETA));
                if (s < 0) s = 0;
                if (s > 30) s = 30;
            }
            s_squarings = s;
        }
        __syncthreads();
    }
    const int nsq = s_squarings;
    const float scale = exp2f((float)-nsq);

    // ---- scale A ----
    for (int e = tid; e < NN; e += THREADS) bA[e] *= scale;
    __syncthreads();

    // ---- powers: A2, A3, A4 ----
    mm64<false>(bA2, bA,  bA);  __syncthreads();
    mm64<false>(bA3, bA2, bA);  __syncthreads();
    mm64<false>(bA4, bA2, bA2); __syncthreads();

    // Taylor coefficients 1/k!
    const float c0  = 1.0f;
    const float c1  = 1.0f;
    const float c2  = 0.5f;
    const float c3  = (float)(1.0 / 6.0);
    const float c4  = (float)(1.0 / 24.0);
    const float c5  = (float)(1.0 / 120.0);
    const float c6  = (float)(1.0 / 720.0);
    const float c7  = (float)(1.0 / 5040.0);
    const float c8  = (float)(1.0 / 40320.0);
    const float c9  = (float)(1.0 / 362880.0);
    const float c10 = (float)(1.0 / 3628800.0);
    const float c11 = (float)(1.0 / 39916800.0);
    const float c12 = (float)(1.0 / 479001600.0);
    const float c13 = (float)(1.0 / 6227020800.0);
    const float c14 = (float)(1.0 / 87178291200.0);
    const float c15 = (float)(1.0 / 1307674368000.0);
    const float c16 = (float)(1.0 / 20922789888000.0);

    // ---- S = c12 I + c13 A + c14 A2 + c15 A3 + c16 A4 (top Horner block) ----
    for (int e = tid; e < NN; e += THREADS) {
        float v = fmaf(c13, bA[e], fmaf(c14, bA2[e], fmaf(c15, bA3[e], c16 * bA4[e])));
        if ((e >> 6) == (e & 63)) v += c12;
        bS[e] = v;
    }
    __syncthreads();

    // ---- Horner with fused block epilogues ----
    // S2 = A4*S + (c8 I + c9 A + c10 A2 + c11 A3)
    mm64<true>(bS2, bA4, bS, bA, bA2, bA3, c8, c9, c10, c11);
    __syncthreads();
    // S = A4*S2 + (c4 I + c5 A + c6 A2 + c7 A3)
    mm64<true>(bS, bA4, bS2, bA, bA2, bA3, c4, c5, c6, c7);
    __syncthreads();
    // S2 = A4*S + (c0 I + c1 A + c2 A2 + c3 A3)   == T16(A_scaled)
    mm64<true>(bS2, bA4, bS, bA, bA2, bA3, c0, c1, c2, c3);
    __syncthreads();

    // ---- Squarings: X = X^(2^s), ping-pong bS2 <-> bS ----
    float* src = bS2;
    float* dst = bS;
    for (int t = 0; t < nsq; t++) {
        mm64<false>(dst, src, src);
        __syncthreads();
        float* tmp = src; src = dst; dst = tmp;
    }

    // ---- Write result ----
    for (int e = tid; e < NN; e += THREADS) Ob[e] = src[e];
}

extern "C" void kernel_launch(void* const* d_in, const int* in_sizes, int n_in,
                              void* d_out, int out_size) {
    const float* R = (const float*)d_in[0];
    const float* G = (const float*)d_in[1];
    float* out = (float*)d_out;

    const int batch = in_sizes[0] / NN;   // 8192
    const size_t smem = 6 * NN * sizeof(float);  // 96 KB

    static bool attr_set = false;
    if (!attr_set) {
        cudaFuncSetAttribute(meg_update_kernel,
                             cudaFuncAttributeMaxDynamicSharedMemorySize,
                             (int)smem);
        attr_set = true;
    }

    meg_update_kernel<<<batch, THREADS, smem>>>(R, G, out);
}